// round 1
// baseline (speedup 1.0000x reference)
#include <cuda_runtime.h>
#include <math_constants.h>

#define NUM_C 8192
#define NUM_B 256
#define NTHREADS 256
#define EPSF 1e-6f

// per-row loss scratch (allocation-free rule: __device__ global)
__device__ float g_row_loss[NUM_B];

__global__ __launch_bounds__(NTHREADS)
void seesaw_row_kernel(const float* __restrict__ logits,
                       const float* __restrict__ targets,
                       const float* __restrict__ s)
{
    __shared__ float sh_logits[NUM_C];     // 32 KB row stage
    __shared__ float red[NTHREADS];
    __shared__ int   sh_label;
    __shared__ float sh_elab;

    const int b   = blockIdx.x;
    const int tid = threadIdx.x;

    const float4* lg4 = (const float4*)(logits  + (size_t)b * NUM_C);
    const float4* tg4 = (const float4*)(targets + (size_t)b * NUM_C);
    float4* shl4 = (float4*)sh_logits;

    // ---- pass 1: stage logits to smem, row max, find one-hot label ----
    float lmax = -CUDART_INF_F;
    int label = -1;
    #pragma unroll
    for (int i = 0; i < NUM_C / 4 / NTHREADS; i++) {   // 8 iters
        int idx4 = tid + i * NTHREADS;
        float4 v = lg4[idx4];
        float4 t = tg4[idx4];
        shl4[idx4] = v;
        lmax = fmaxf(lmax, fmaxf(fmaxf(v.x, v.y), fmaxf(v.z, v.w)));
        int j = idx4 * 4;
        if (t.x > 0.5f) label = j + 0;
        if (t.y > 0.5f) label = j + 1;
        if (t.z > 0.5f) label = j + 2;
        if (t.w > 0.5f) label = j + 3;
    }
    if (label >= 0) sh_label = label;

    red[tid] = lmax;
    __syncthreads();
    #pragma unroll
    for (int off = NTHREADS / 2; off > 0; off >>= 1) {
        if (tid < off) red[tid] = fmaxf(red[tid], red[tid + off]);
        __syncthreads();
    }
    const float rowmax = red[0];
    const int   lab    = sh_label;
    __syncthreads();   // before reusing red[]

    // ---- pass 2: denom = dot(s[lab,:], exp(logits - max))  (s diag == 1
    // makes this exactly the reference's masked sum + expl term) ----
    const float4* s4 = (const float4*)(s + (size_t)lab * NUM_C);
    float acc = 0.f;
    #pragma unroll
    for (int i = 0; i < NUM_C / 4 / NTHREADS; i++) {
        int idx4 = tid + i * NTHREADS;
        float4 v  = shl4[idx4];
        float4 sv = s4[idx4];
        float e0 = __expf(v.x - rowmax);
        float e1 = __expf(v.y - rowmax);
        float e2 = __expf(v.z - rowmax);
        float e3 = __expf(v.w - rowmax);
        acc += sv.x * e0 + sv.y * e1 + sv.z * e2 + sv.w * e3;
        int j = idx4 * 4;
        if (j + 0 == lab) sh_elab = e0;
        if (j + 1 == lab) sh_elab = e1;
        if (j + 2 == lab) sh_elab = e2;
        if (j + 3 == lab) sh_elab = e3;
    }

    red[tid] = acc;
    __syncthreads();
    #pragma unroll
    for (int off = NTHREADS / 2; off > 0; off >>= 1) {
        if (tid < off) red[tid] = red[tid] + red[tid + off];
        __syncthreads();
    }

    if (tid == 0) {
        float denom = red[0];                 // includes 1*e_lab diagonal term
        float elab  = sh_elab;
        float sigma = elab / (denom + EPSF);
        g_row_loss[b] = -logf(sigma + EPSF);
    }
}

__global__ __launch_bounds__(NTHREADS)
void seesaw_mean_kernel(float* __restrict__ out)
{
    __shared__ float red[NTHREADS];
    int tid = threadIdx.x;
    red[tid] = g_row_loss[tid];               // NUM_B == NTHREADS
    __syncthreads();
    #pragma unroll
    for (int off = NTHREADS / 2; off > 0; off >>= 1) {
        if (tid < off) red[tid] = red[tid] + red[tid + off];
        __syncthreads();
    }
    if (tid == 0) out[0] = red[0] / (float)NUM_B;
}

extern "C" void kernel_launch(void* const* d_in, const int* in_sizes, int n_in,
                              void* d_out, int out_size)
{
    const float* logits  = (const float*)d_in[0];
    const float* targets = (const float*)d_in[1];
    const float* s       = (const float*)d_in[2];
    float* out = (float*)d_out;

    seesaw_row_kernel<<<NUM_B, NTHREADS>>>(logits, targets, s);
    seesaw_mean_kernel<<<1, NTHREADS>>>(out);
}

// round 2
// speedup vs baseline: 1.1841x; 1.1841x over previous
#include <cuda_runtime.h>

#define NUM_C 8192
#define NUM_B 256
#define NT    512
#define EPSF  1e-6f
#define NWARP (NT / 32)

// cross-block accumulators (allocation-free rule: __device__ globals)
__device__ float        g_sum   = 0.0f;
__device__ unsigned int g_count = 0u;

__global__ __launch_bounds__(NT)
void seesaw_fused_kernel(const float* __restrict__ logits,
                         const float* __restrict__ targets,
                         const float* __restrict__ s,
                         float* __restrict__ out)
{
    __shared__ float sh_e[NUM_C];        // 32 KB: exp(logits) row stage
    __shared__ float sh_warp[NWARP];
    __shared__ int   sh_label;
    __shared__ float sh_elab;

    const int b    = blockIdx.x;
    const int tid  = threadIdx.x;
    const int lane = tid & 31;
    const int wid  = tid >> 5;

    const float4* lg4 = (const float4*)(logits  + (size_t)b * NUM_C);
    const float4* tg4 = (const float4*)(targets + (size_t)b * NUM_C);
    float4* she4 = (float4*)sh_e;

    // ---- phase 1: e = exp(logits) staged to smem; find one-hot label + e_lab ----
    // (no max shift: it only rescales the +eps in sigma's denominator by
    //  e^{-max} ~ 0.02, a ~1e-8 relative perturbation of sigma — negligible)
    #pragma unroll
    for (int i = 0; i < NUM_C / 4 / NT; i++) {          // 4 iters
        int idx4 = tid + i * NT;
        float4 v = lg4[idx4];
        float4 t = tg4[idx4];
        float4 e;
        e.x = __expf(v.x); e.y = __expf(v.y);
        e.z = __expf(v.z); e.w = __expf(v.w);
        she4[idx4] = e;
        int j = idx4 * 4;
        if (t.x > 0.5f) { sh_label = j + 0; sh_elab = e.x; }
        if (t.y > 0.5f) { sh_label = j + 1; sh_elab = e.y; }
        if (t.z > 0.5f) { sh_label = j + 2; sh_elab = e.z; }
        if (t.w > 0.5f) { sh_label = j + 3; sh_elab = e.w; }
    }
    __syncthreads();
    const int lab = sh_label;

    // ---- phase 2: denom = dot(s[lab,:], e)  (s diag == 1 folds in the +expl term) ----
    const float4* s4 = (const float4*)(s + (size_t)lab * NUM_C);
    float acc = 0.f;
    #pragma unroll
    for (int i = 0; i < NUM_C / 4 / NT; i++) {          // 4 iters
        int idx4 = tid + i * NT;
        float4 sv = s4[idx4];
        float4 e  = she4[idx4];
        acc += sv.x * e.x + sv.y * e.y + sv.z * e.z + sv.w * e.w;
    }

    // warp reduce, then cross-warp reduce
    #pragma unroll
    for (int off = 16; off > 0; off >>= 1)
        acc += __shfl_down_sync(0xffffffffu, acc, off);
    if (lane == 0) sh_warp[wid] = acc;
    __syncthreads();

    if (wid == 0) {
        float v = (lane < NWARP) ? sh_warp[lane] : 0.f;
        #pragma unroll
        for (int off = 8; off > 0; off >>= 1)
            v += __shfl_down_sync(0xffffffffu, v, off);

        if (lane == 0) {
            float denom = v;
            float sigma = sh_elab / (denom + EPSF);
            float loss  = -logf(sigma + EPSF);
            atomicAdd(&g_sum, loss);
            __threadfence();
            unsigned int tkt = atomicAdd(&g_count, 1u);
            if (tkt == NUM_B - 1u) {
                // all 256 contributions fenced+visible; drain & reset for next replay
                float total = atomicExch(&g_sum, 0.0f);
                g_count = 0u;
                out[0] = total * (1.0f / NUM_B);
            }
        }
    }
}

extern "C" void kernel_launch(void* const* d_in, const int* in_sizes, int n_in,
                              void* d_out, int out_size)
{
    const float* logits  = (const float*)d_in[0];
    const float* targets = (const float*)d_in[1];
    const float* s       = (const float*)d_in[2];
    float* out = (float*)d_out;

    seesaw_fused_kernel<<<NUM_B, NT>>>(logits, targets, s, out);
}